// round 2
// baseline (speedup 1.0000x reference)
#include <cuda_runtime.h>
#include <math.h>

#define NUM_NODES 17185
#define D 6
#define FEATS (NUM_NODES * D)   // 103110
#define BATCH 256
#define NODES_PER_BLOCK 64
#define NBLK ((NUM_NODES + NODES_PER_BLOCK - 1) / NODES_PER_BLOCK)  // 269
#define EPS 1e-5f

// Per-block partial sums for each batch row. Written unconditionally by every
// block each launch (no stale data, no init needed). __device__ global => no
// allocation inside kernel_launch.
__device__ float g_partial[NBLK * BATCH];

__global__ __launch_bounds__(256, 2)
void node_block_kernel(const float* __restrict__ data,
                       const float* __restrict__ w_blocks,
                       const float* __restrict__ b_blocks,
                       const float* __restrict__ bn_gamma,
                       const float* __restrict__ bn_beta,
                       const float* __restrict__ bn_mean,
                       const float* __restrict__ bn_var,
                       const float* __restrict__ fc_w)
{
    __shared__ float sh_acc[BATCH];
    const int tid = threadIdx.x;
    sh_acc[tid] = 0.0f;
    __syncthreads();

    const int ln    = tid & 63;        // node lane within block
    const int group = tid >> 6;        // 0..3 -> batch sub-row
    const int node  = blockIdx.x * NODES_PER_BLOCK + ln;
    const bool valid = (node < NUM_NODES);

    // Per-thread node state, loaded ONCE, reused for all 256 batch rows.
    float W[36];
    float bias[D], A[D], C[D];

    if (valid) {
        // w_blocks[node] : 36 floats = 144 B, 16B-aligned -> 9x float4
        const float4* wp = reinterpret_cast<const float4*>(w_blocks + (size_t)node * 36);
        #pragma unroll
        for (int i = 0; i < 9; ++i) {
            float4 v = __ldg(&wp[i]);
            W[i*4+0] = v.x; W[i*4+1] = v.y; W[i*4+2] = v.z; W[i*4+3] = v.w;
        }
        const int f0 = node * D;
        #pragma unroll
        for (int o = 0; o < D; ++o) {
            const int f = f0 + o;
            bias[o]  = b_blocks[f];
            const float rs = rsqrtf(bn_var[f] + EPS);
            const float g  = bn_gamma[f] * rs;
            const float fw = fc_w[f];
            A[o] = g * fw;
            C[o] = (bn_beta[f] - bn_mean[f] * g) * fw;
        }
    }

    const float* dbase = data + (size_t)node * D;  // only deref'd when valid

    #pragma unroll 4
    for (int bi = 0; bi < BATCH / 4; ++bi) {
        const int b = bi * 4 + group;
        float acc = 0.0f;
        if (valid) {
            // 24 B node slice of row b: 3x float2 (offset node*24 is 8B-aligned)
            const float2* xp = reinterpret_cast<const float2*>(dbase + (size_t)b * FEATS);
            const float2 x01 = __ldg(&xp[0]);
            const float2 x23 = __ldg(&xp[1]);
            const float2 x45 = __ldg(&xp[2]);
            const float x[D] = {x01.x, x01.y, x23.x, x23.y, x45.x, x45.y};
            #pragma unroll
            for (int o = 0; o < D; ++o) {
                float s = bias[o];
                #pragma unroll
                for (int i = 0; i < D; ++i)
                    s = fmaf(x[i], W[o * D + i], s);
                s = fmaxf(s, 0.0f);               // ReLU
                acc = fmaf(s, A[o], acc + C[o]);  // folded BN * fc_w
            }
        }
        // Warp reduce: all 32 lanes of a warp share the same b.
        #pragma unroll
        for (int off = 16; off > 0; off >>= 1)
            acc += __shfl_xor_sync(0xffffffffu, acc, off);
        if ((tid & 31) == 0)
            atomicAdd(&sh_acc[b], acc);  // exactly 2 adds per b -> order-invariant
    }
    __syncthreads();
    g_partial[blockIdx.x * BATCH + tid] = sh_acc[tid];
}

__global__ void finalize_kernel(const float* __restrict__ fc_b,
                                const float* __restrict__ bnf_gamma,
                                const float* __restrict__ bnf_beta,
                                const float* __restrict__ bnf_mean,
                                const float* __restrict__ bnf_var,
                                float* __restrict__ out)
{
    const int b = threadIdx.x;  // 256 threads, one per batch row
    float s = fc_b[0];
    #pragma unroll 8
    for (int k = 0; k < NBLK; ++k)       // fixed order -> deterministic
        s += g_partial[k * BATCH + b];   // coalesced across threads
    const float rs = rsqrtf(bnf_var[0] + EPS);
    const float y  = (s - bnf_mean[0]) * rs * bnf_gamma[0] + bnf_beta[0];
    out[b] = 1.0f / (1.0f + expf(-y));
}

extern "C" void kernel_launch(void* const* d_in, const int* in_sizes, int n_in,
                              void* d_out, int out_size) {
    const float* data      = (const float*)d_in[0];
    const float* w_blocks  = (const float*)d_in[1];
    const float* b_blocks  = (const float*)d_in[2];
    const float* bn_gamma  = (const float*)d_in[3];
    const float* bn_beta   = (const float*)d_in[4];
    const float* bn_mean   = (const float*)d_in[5];
    const float* bn_var    = (const float*)d_in[6];
    const float* fc_w      = (const float*)d_in[7];
    const float* fc_b      = (const float*)d_in[8];
    const float* bnf_gamma = (const float*)d_in[9];
    const float* bnf_beta  = (const float*)d_in[10];
    const float* bnf_mean  = (const float*)d_in[11];
    const float* bnf_var   = (const float*)d_in[12];
    float* out = (float*)d_out;

    node_block_kernel<<<NBLK, 256>>>(data, w_blocks, b_blocks, bn_gamma,
                                     bn_beta, bn_mean, bn_var, fc_w);
    finalize_kernel<<<1, 256>>>(fc_b, bnf_gamma, bnf_beta, bnf_mean, bnf_var, out);
}

// round 3
// speedup vs baseline: 1.2383x; 1.2383x over previous
#include <cuda_runtime.h>
#include <math.h>

#define NUM_NODES 17185
#define D 6
#define FEATS (NUM_NODES * D)   // 103110
#define BATCH 256
#define NODES_PER_BLOCK 64
#define NBLK ((NUM_NODES + NODES_PER_BLOCK - 1) / NODES_PER_BLOCK)  // 269
#define EPS 1e-5f

// Per-block partial sums for each batch row, written unconditionally every
// launch. __device__ global => no allocation inside kernel_launch.
__device__ float g_partial[NBLK * BATCH];

__global__ __launch_bounds__(256, 2)
void node_block_kernel(const float* __restrict__ data,
                       const float* __restrict__ w_blocks,
                       const float* __restrict__ b_blocks,
                       const float* __restrict__ bn_gamma,
                       const float* __restrict__ bn_beta,
                       const float* __restrict__ bn_mean,
                       const float* __restrict__ bn_var,
                       const float* __restrict__ fc_w)
{
    __shared__ float sh_part[8][64];   // [warp][bi] warp partial sums

    const int tid   = threadIdx.x;
    const int ln    = tid & 63;        // node lane within block
    const int group = tid >> 6;        // 0..3 -> batch sub-row
    const int warp  = tid >> 5;        // 0..7
    const int lane  = tid & 31;
    const int node  = blockIdx.x * NODES_PER_BLOCK + ln;
    const bool valid = (node < NUM_NODES);

    // Per-thread node state, loaded ONCE, reused for all 256 batch rows.
    float W[36];
    float bias[D], A[D];
    float CN = 0.0f;   // sum_o (beta - mean*g) * fc_w  (constant per node)

    if (valid) {
        const float4* wp = reinterpret_cast<const float4*>(w_blocks + (size_t)node * 36);
        #pragma unroll
        for (int i = 0; i < 9; ++i) {
            float4 v = __ldg(&wp[i]);
            W[i*4+0] = v.x; W[i*4+1] = v.y; W[i*4+2] = v.z; W[i*4+3] = v.w;
        }
        const int f0 = node * D;
        #pragma unroll
        for (int o = 0; o < D; ++o) {
            const int f = f0 + o;
            bias[o] = b_blocks[f];
            const float rs = rsqrtf(bn_var[f] + EPS);
            const float g  = bn_gamma[f] * rs;
            const float fw = fc_w[f];
            A[o]  = g * fw;
            CN   += (bn_beta[f] - bn_mean[f] * g) * fw;
        }
    }

    const float* dbase = data + (size_t)node * D;  // only deref'd when valid

    float r0 = 0.0f, r1 = 0.0f;  // captured warp sums for bi = lane, lane+32

    #pragma unroll 4
    for (int bi = 0; bi < BATCH / 4; ++bi) {
        const int b = bi * 4 + group;
        float acc = 0.0f;
        if (valid) {
            const float2* xp = reinterpret_cast<const float2*>(dbase + (size_t)b * FEATS);
            const float2 x01 = __ldg(&xp[0]);
            const float2 x23 = __ldg(&xp[1]);
            const float2 x45 = __ldg(&xp[2]);
            const float x[D] = {x01.x, x01.y, x23.x, x23.y, x45.x, x45.y};
            acc = CN;
            #pragma unroll
            for (int o = 0; o < D; ++o) {
                float s = bias[o];
                #pragma unroll
                for (int i = 0; i < D; ++i)
                    s = fmaf(x[i], W[o * D + i], s);
                s = fmaxf(s, 0.0f);        // ReLU
                acc = fmaf(s, A[o], acc);  // folded BN * fc_w (C folded into CN)
            }
        }
        // Warp reduce: all 32 lanes share the same b. Butterfly -> every lane
        // holds the warp sum; lane (bi&31) keeps it in a register. No atomics.
        #pragma unroll
        for (int off = 16; off > 0; off >>= 1)
            acc += __shfl_xor_sync(0xffffffffu, acc, off);
        const bool take = (lane == (bi & 31));
        if (bi < 32) r0 = take ? acc : r0;
        else         r1 = take ? acc : r1;
    }

    sh_part[warp][lane]      = r0;
    sh_part[warp][lane + 32] = r1;
    __syncthreads();

    // Deterministic combine: b = tid -> (g = b&3, bi = b>>2); warps 2g and
    // 2g+1 processed node halves for the same b.
    {
        const int b  = tid;
        const int g  = b & 3;
        const int bi = b >> 2;
        g_partial[blockIdx.x * BATCH + b] = sh_part[2*g][bi] + sh_part[2*g+1][bi];
    }
}

__global__ void finalize_kernel(const float* __restrict__ fc_b,
                                const float* __restrict__ bnf_gamma,
                                const float* __restrict__ bnf_beta,
                                const float* __restrict__ bnf_mean,
                                const float* __restrict__ bnf_var,
                                float* __restrict__ out)
{
    const int b    = blockIdx.x;    // one block per batch row
    const int tid  = threadIdx.x;   // 64 threads
    const int lane = tid & 31;
    const int warp = tid >> 5;
    __shared__ float sh[2];

    float s = 0.0f;
    #pragma unroll 5
    for (int k = tid; k < NBLK; k += 64)          // fixed order -> deterministic
        s += g_partial[k * BATCH + b];

    #pragma unroll
    for (int off = 16; off > 0; off >>= 1)
        s += __shfl_xor_sync(0xffffffffu, s, off);
    if (lane == 0) sh[warp] = s;
    __syncthreads();

    if (tid == 0) {
        float t = sh[0] + sh[1] + fc_b[0];
        const float rs = rsqrtf(bnf_var[0] + EPS);
        const float y  = (t - bnf_mean[0]) * rs * bnf_gamma[0] + bnf_beta[0];
        out[b] = 1.0f / (1.0f + expf(-y));
    }
}

extern "C" void kernel_launch(void* const* d_in, const int* in_sizes, int n_in,
                              void* d_out, int out_size) {
    const float* data      = (const float*)d_in[0];
    const float* w_blocks  = (const float*)d_in[1];
    const float* b_blocks  = (const float*)d_in[2];
    const float* bn_gamma  = (const float*)d_in[3];
    const float* bn_beta   = (const float*)d_in[4];
    const float* bn_mean   = (const float*)d_in[5];
    const float* bn_var    = (const float*)d_in[6];
    const float* fc_w      = (const float*)d_in[7];
    const float* fc_b      = (const float*)d_in[8];
    const float* bnf_gamma = (const float*)d_in[9];
    const float* bnf_beta  = (const float*)d_in[10];
    const float* bnf_mean  = (const float*)d_in[11];
    const float* bnf_var   = (const float*)d_in[12];
    float* out = (float*)d_out;

    node_block_kernel<<<NBLK, 256>>>(data, w_blocks, b_blocks, bn_gamma,
                                     bn_beta, bn_mean, bn_var, fc_w);
    finalize_kernel<<<BATCH, 64>>>(fc_b, bnf_gamma, bnf_beta, bnf_mean, bnf_var, out);
}